// round 1
// baseline (speedup 1.0000x reference)
#include <cuda_runtime.h>
#include <cstdint>

// FeatureEmbeddingBank: B=4096, 25 regular + 25 compressed tables, L=20, D=64.
// One warp per (b, f) bag. Lanes 0..19 own one index each; each lane owns a
// float2 (8B) column slice of the D=64 row. Fully unrolled gather loop for
// high MLP (DRAM-latency hiding). Padding row 0 is all-zero in both tables,
// so idx==0 gathers are harmless -> branch-free.

#define F_REG 25
#define F_TOT 50
#define L_LEN 20
#define EMB_D 64
#define V_REG 50000
#define N_BUCKETS 100000

__global__ __launch_bounds__(256, 8)
void feat_bag_kernel(const int* __restrict__ feats,
                     const float* __restrict__ W_reg,
                     const float* __restrict__ W_cmp,
                     float* __restrict__ out,
                     int n_bags)
{
    const int warp_global = (blockIdx.x * blockDim.x + threadIdx.x) >> 5;
    const int lane = threadIdx.x & 31;
    if (warp_global >= n_bags) return;

    const int b = warp_global / F_TOT;
    const int f = warp_global - b * F_TOT;

    // --- load + map this lane's index (lanes 0..19) ---
    int raw = 0;
    if (lane < L_LEN)
        raw = __ldg(feats + (size_t)b * (F_TOT * L_LEN) + f * L_LEN + lane);

    int idx;
    const float* table;
    if (f < F_REG) {
        idx = min(max(raw, 0), V_REG);
        table = W_reg + (size_t)f * (V_REG + 1) * EMB_D;
    } else {
        int v = max(raw, 0);
        idx = (v > 0) ? ((v - 1) % N_BUCKETS) + 1 : 0;
        table = W_cmp + (size_t)(f - F_REG) * (N_BUCKETS + 1) * EMB_D;
    }

    // nonzero count (mapped idx>0 <=> raw>0 for both table kinds)
    const unsigned pos = __ballot_sync(0xffffffffu, (lane < L_LEN) && (idx > 0));
    const float inv_cnt = 1.0f / (float)max(__popc(pos), 1);

    // --- gather + accumulate, fully unrolled for MLP ---
    float2 acc = make_float2(0.0f, 0.0f);
#pragma unroll
    for (int i = 0; i < L_LEN; ++i) {
        const int ri = __shfl_sync(0xffffffffu, idx, i);
        const float2 v = __ldg(
            reinterpret_cast<const float2*>(table + (size_t)ri * EMB_D) + lane);
        acc.x += v.x;
        acc.y += v.y;
    }

    acc.x *= inv_cnt;
    acc.y *= inv_cnt;
    reinterpret_cast<float2*>(out + (size_t)warp_global * EMB_D)[lane] = acc;
}

extern "C" void kernel_launch(void* const* d_in, const int* in_sizes, int n_in,
                              void* d_out, int out_size)
{
    const int*   feats = (const int*)d_in[0];     // [B, 1000] int32
    const float* W_reg = (const float*)d_in[1];   // [25, 50001, 64] f32
    const float* W_cmp = (const float*)d_in[2];   // [25, 100001, 64] f32
    float*       out   = (float*)d_out;           // [B, 50, 64] f32

    const int B = in_sizes[0] / (F_TOT * L_LEN);
    const int n_bags = B * F_TOT;                 // 204800
    const int threads = 256;                      // 8 warps = 8 bags / block
    const int blocks = (n_bags * 32 + threads - 1) / threads;

    feat_bag_kernel<<<blocks, threads>>>(feats, W_reg, W_cmp, out, n_bags);
}

// round 2
// speedup vs baseline: 1.0021x; 1.0021x over previous
#include <cuda_runtime.h>
#include <cstdint>

// FeatureEmbeddingBank: B=4096, 25 regular + 25 compressed tables, L=20, D=64.
// One warp per (b, f) bag. Lanes 0..19 own one index each (broadcast via shfl).
// Gather phase: 2 rows per iteration -- lanes 0..15 take row 2i as float4,
// lanes 16..31 take row 2i+1. 10x LDG.128 per thread, fully unrolled for MLP.
// Final cross-half reduce via shfl_xor(16); lanes 0..15 store the 256B bag.
// Padding row 0 is all-zero in both tables -> branch-free gather.

#define F_REG 25
#define F_TOT 50
#define L_LEN 20
#define EMB_D 64
#define V_REG 50000
#define N_BUCKETS 100000

__global__ __launch_bounds__(256)
void feat_bag_kernel(const int* __restrict__ feats,
                     const float* __restrict__ W_reg,
                     const float* __restrict__ W_cmp,
                     float* __restrict__ out,
                     int n_bags)
{
    const int warp_global = (blockIdx.x * blockDim.x + threadIdx.x) >> 5;
    const int lane = threadIdx.x & 31;
    if (warp_global >= n_bags) return;

    const int b = warp_global / F_TOT;
    const int f = warp_global - b * F_TOT;

    // --- load + map this lane's index (lanes 0..19) ---
    int raw = 0;
    if (lane < L_LEN)
        raw = __ldg(feats + (size_t)b * (F_TOT * L_LEN) + f * L_LEN + lane);

    int idx;
    const float* table;
    if (f < F_REG) {
        idx = min(max(raw, 0), V_REG);
        table = W_reg + (size_t)f * (V_REG + 1) * EMB_D;
    } else {
        int v = max(raw, 0);
        idx = (v > 0) ? ((v - 1) % N_BUCKETS) + 1 : 0;
        table = W_cmp + (size_t)(f - F_REG) * (N_BUCKETS + 1) * EMB_D;
    }

    // nonzero count (mapped idx>0 <=> raw>0 for both table kinds)
    const unsigned pos = __ballot_sync(0xffffffffu, (lane < L_LEN) && (idx > 0));
    const float inv_cnt = 1.0f / (float)max(__popc(pos), 1);

    // --- gather + accumulate: 2 rows per iter, float4 per thread ---
    const int half = lane >> 4;          // 0: even rows, 1: odd rows
    const int col  = lane & 15;          // float4 column within the row
    float4 acc = make_float4(0.0f, 0.0f, 0.0f, 0.0f);

#pragma unroll
    for (int i = 0; i < L_LEN / 2; ++i) {
        const int ri = __shfl_sync(0xffffffffu, idx, 2 * i + half);
        const float4 v = __ldg(
            reinterpret_cast<const float4*>(table + (size_t)ri * EMB_D) + col);
        acc.x += v.x; acc.y += v.y; acc.z += v.z; acc.w += v.w;
    }

    // combine even-row half with odd-row half (same column, lane ^ 16)
    acc.x += __shfl_xor_sync(0xffffffffu, acc.x, 16);
    acc.y += __shfl_xor_sync(0xffffffffu, acc.y, 16);
    acc.z += __shfl_xor_sync(0xffffffffu, acc.z, 16);
    acc.w += __shfl_xor_sync(0xffffffffu, acc.w, 16);

    if (half == 0) {
        acc.x *= inv_cnt; acc.y *= inv_cnt; acc.z *= inv_cnt; acc.w *= inv_cnt;
        reinterpret_cast<float4*>(out + (size_t)warp_global * EMB_D)[col] = acc;
    }
}

extern "C" void kernel_launch(void* const* d_in, const int* in_sizes, int n_in,
                              void* d_out, int out_size)
{
    const int*   feats = (const int*)d_in[0];     // [B, 1000] int32
    const float* W_reg = (const float*)d_in[1];   // [25, 50001, 64] f32
    const float* W_cmp = (const float*)d_in[2];   // [25, 100001, 64] f32
    float*       out   = (float*)d_out;           // [B, 50, 64] f32

    const int B = in_sizes[0] / (F_TOT * L_LEN);
    const int n_bags = B * F_TOT;                 // 204800
    const int threads = 256;                      // 8 warps = 8 bags / block
    const int blocks = (n_bags * 32 + threads - 1) / threads;

    feat_bag_kernel<<<blocks, threads>>>(feats, W_reg, W_cmp, out, n_bags);
}

// round 7
// speedup vs baseline: 1.0215x; 1.0194x over previous
#include <cuda_runtime.h>
#include <cstdint>

// FeatureEmbeddingBank: B=4096, 25 regular + 25 compressed tables, L=20, D=64.
// One warp per bag, f-major enumeration (bag = f*B + b): all concurrently
// resident warps hammer the same ~14MB table, so repeated rows are L2-resident
// (126MB L2) instead of re-fetched from DRAM. Output written b-major.
// Gather: 2 rows/iter, float4/lane, unrolled; shfl_xor(16) combine.
// (Resubmission: R3 harness timeout, R4-R6 GPU-acquisition timeouts — all
//  infra; this kernel variant has not yet been measured.)

#define F_REG 25
#define F_TOT 50
#define L_LEN 20
#define EMB_D 64
#define V_REG 50000
#define N_BUCKETS 100000

__global__ __launch_bounds__(256)
void feat_bag_kernel(const int* __restrict__ feats,
                     const float* __restrict__ W_reg,
                     const float* __restrict__ W_cmp,
                     float* __restrict__ out,
                     int n_bags, int B, int b_shift)
{
    const int warp_global = (blockIdx.x * blockDim.x + threadIdx.x) >> 5;
    const int lane = threadIdx.x & 31;
    if (warp_global >= n_bags) return;

    // f-major enumeration; B is a power of two in this problem (4096)
    int f, b;
    if (b_shift >= 0) {
        f = warp_global >> b_shift;
        b = warp_global & (B - 1);
    } else {
        f = warp_global / B;
        b = warp_global - f * B;
    }

    // --- load + map this lane's index (lanes 0..19) ---
    int raw = 0;
    if (lane < L_LEN)
        raw = __ldg(feats + (size_t)b * (F_TOT * L_LEN) + f * L_LEN + lane);

    int idx;
    const float* table;
    if (f < F_REG) {
        idx = min(max(raw, 0), V_REG);
        table = W_reg + (size_t)f * (V_REG + 1) * EMB_D;
    } else {
        int v = max(raw, 0);
        idx = (v > 0) ? ((v - 1) % N_BUCKETS) + 1 : 0;
        table = W_cmp + (size_t)(f - F_REG) * (N_BUCKETS + 1) * EMB_D;
    }

    // nonzero count (mapped idx>0 <=> raw>0 for both table kinds)
    const unsigned pos = __ballot_sync(0xffffffffu, (lane < L_LEN) && (idx > 0));
    const float inv_cnt = 1.0f / (float)max(__popc(pos), 1);

    // --- gather + accumulate: 2 rows per iter, float4 per thread ---
    const int half = lane >> 4;          // 0: even rows, 1: odd rows
    const int col  = lane & 15;          // float4 column within the row
    float4 acc = make_float4(0.0f, 0.0f, 0.0f, 0.0f);

#pragma unroll
    for (int i = 0; i < L_LEN / 2; ++i) {
        const int ri = __shfl_sync(0xffffffffu, idx, 2 * i + half);
        const float4 v = __ldg(
            reinterpret_cast<const float4*>(table + (size_t)ri * EMB_D) + col);
        acc.x += v.x; acc.y += v.y; acc.z += v.z; acc.w += v.w;
    }

    // combine even-row half with odd-row half (same column, lane ^ 16)
    acc.x += __shfl_xor_sync(0xffffffffu, acc.x, 16);
    acc.y += __shfl_xor_sync(0xffffffffu, acc.y, 16);
    acc.z += __shfl_xor_sync(0xffffffffu, acc.z, 16);
    acc.w += __shfl_xor_sync(0xffffffffu, acc.w, 16);

    if (half == 0) {
        acc.x *= inv_cnt; acc.y *= inv_cnt; acc.z *= inv_cnt; acc.w *= inv_cnt;
        // output stays b-major: [B, 50, D]
        reinterpret_cast<float4*>(out + ((size_t)b * F_TOT + f) * EMB_D)[col] = acc;
    }
}

extern "C" void kernel_launch(void* const* d_in, const int* in_sizes, int n_in,
                              void* d_out, int out_size)
{
    const int*   feats = (const int*)d_in[0];     // [B, 1000] int32
    const float* W_reg = (const float*)d_in[1];   // [25, 50001, 64] f32
    const float* W_cmp = (const float*)d_in[2];   // [25, 100001, 64] f32
    float*       out   = (float*)d_out;           // [B, 50, 64] f32

    const int B = in_sizes[0] / (F_TOT * L_LEN);
    // power-of-two fast path (B=4096 here)
    int b_shift = -1;
    if ((B & (B - 1)) == 0) {
        b_shift = 0;
        while ((1 << b_shift) < B) ++b_shift;
    }

    const int n_bags = B * F_TOT;                 // 204800
    const int threads = 256;                      // 8 warps = 8 bags / block
    const int blocks = (n_bags * 32 + threads - 1) / threads;

    feat_bag_kernel<<<blocks, threads>>>(feats, W_reg, W_cmp, out,
                                         n_bags, B, b_shift);
}